// round 3
// baseline (speedup 1.0000x reference)
#include <cuda_runtime.h>

#define HH 512
#define WW 512
#define NIMG 24            // 8 * 3 planes
#define KS 121
#define KPAD 128           // taps padded with zero weights for unroll-8 ring
#define MEANR 60

__device__ float g_w[KPAD];
__device__ float g_tmp[NIMG * HH * WW];

// ---------------------------------------------------------------------------
// Compute normalized 1D Gaussian weights from sigma (on device).
// w[i] = e_i / sum(e).  Two passes of w reproduce gk2d = e_i e_j / (sum e)^2.
// ---------------------------------------------------------------------------
__global__ void weights_kernel(const float* __restrict__ sigma) {
    __shared__ float se[128];
    int i = threadIdx.x;
    float s = sigma[0] * 8.0f + 16.0f;
    float var = s * s;
    float e = 0.0f;
    if (i < KS) {
        float d = (float)(i - MEANR);
        e = expf(-(d * d) / (2.0f * var));
    }
    se[i] = e;
    __syncthreads();
    #pragma unroll
    for (int off = 64; off > 0; off >>= 1) {
        if (i < off) se[i] += se[i + off];
        __syncthreads();
    }
    float inv = 1.0f / se[0];
    if (i < KS) g_w[i] = e * inv;
    else        g_w[i] = 0.0f;
}

// ---------------------------------------------------------------------------
// Horizontal pass: x -> g_tmp.  One block = 4 rows, 64 threads/row,
// 8 contiguous outputs per thread via register ring.
// Shared row swizzled p(i) = i + (i>>5) -> conflict-free for stride-8 bases.
// ---------------------------------------------------------------------------
#define H_ROWS 4
#define H_LOGICAL (WW + KPAD + 8)   // 648 logical entries (covers base+127+7)
#define H_PHYS 672                  // p(647)=667, padded up

__global__ __launch_bounds__(256) void hpass_kernel(const float* __restrict__ x) {
    __shared__ float sw[KPAD];
    __shared__ float srow[H_ROWS][H_PHYS];

    int tid = threadIdx.x;
    if (tid < KPAD) sw[tid] = g_w[tid];

    int r = tid >> 6;          // 0..3 sub-row
    int l = tid & 63;          // lane within row
    long row = (long)blockIdx.x * H_ROWS + r;   // 0..12287
    const float* xr = x + row * WW;

    // load 648 clamped values per row
    for (int i = l; i < H_LOGICAL; i += 64) {
        int src = i - MEANR;
        src = min(max(src, 0), WW - 1);
        srow[r][i + (i >> 5)] = xr[src];
    }
    __syncthreads();

    int base = l * 8;
    float v[8];
    #pragma unroll
    for (int j = 0; j < 7; j++) {
        int idx = base + j;
        v[j] = srow[r][idx + (idx >> 5)];
    }
    float acc[8] = {0.f, 0.f, 0.f, 0.f, 0.f, 0.f, 0.f, 0.f};

    #pragma unroll 8
    for (int t = 0; t < KPAD; t++) {
        int idx = base + t + 7;
        v[(t + 7) & 7] = srow[r][idx + (idx >> 5)];
        float wt = sw[t];
        #pragma unroll
        for (int j = 0; j < 8; j++)
            acc[j] = fmaf(wt, v[(t + j) & 7], acc[j]);
    }

    float* orow = g_tmp + row * WW + base;
    #pragma unroll
    for (int j = 0; j < 8; j++) orow[j] = acc[j];
}

// ---------------------------------------------------------------------------
// Vertical pass: g_tmp -> out.  Tile = 32 cols x 64 rows, 256 threads:
// 8 row-groups x 32 cols, 8 contiguous output rows per thread (register ring).
// Shared tile row-stride 33 -> conflict-free column access.
// ---------------------------------------------------------------------------
#define V_COLS 32
#define V_ROWS 64
#define V_LOAD (V_ROWS + KPAD - 1)   // 191 rows needed (ybase+127+7 = 190)

__global__ __launch_bounds__(256) void vpass_kernel(float* __restrict__ out) {
    __shared__ float sw[KPAD];
    __shared__ float sv[V_LOAD + 1][V_COLS + 1];   // 192 x 33

    int tid = threadIdx.x;
    if (tid < KPAD) sw[tid] = g_w[tid];

    int img  = blockIdx.z;
    int col0 = blockIdx.x * V_COLS;
    int y0   = blockIdx.y * V_ROWS;
    const float* tp = g_tmp + (long)img * HH * WW;

    for (int idx = tid; idx < V_LOAD * V_COLS; idx += 256) {
        int rr = idx >> 5;          // 0..190
        int cc = idx & 31;
        int src = y0 + rr - MEANR;
        src = min(max(src, 0), HH - 1);
        sv[rr][cc] = tp[src * WW + col0 + cc];
    }
    __syncthreads();

    int c = tid & 31;
    int g = tid >> 5;       // 0..7
    int ybase = g * 8;

    float v[8];
    #pragma unroll
    for (int j = 0; j < 7; j++) v[j] = sv[ybase + j][c];
    float acc[8] = {0.f, 0.f, 0.f, 0.f, 0.f, 0.f, 0.f, 0.f};

    #pragma unroll 8
    for (int t = 0; t < KPAD; t++) {
        v[(t + 7) & 7] = sv[ybase + t + 7][c];
        float wt = sw[t];
        #pragma unroll
        for (int j = 0; j < 8; j++)
            acc[j] = fmaf(wt, v[(t + j) & 7], acc[j]);
    }

    float* op = out + (long)img * HH * WW + (long)(y0 + ybase) * WW + col0 + c;
    #pragma unroll
    for (int j = 0; j < 8; j++) op[(long)j * WW] = acc[j];
}

// ---------------------------------------------------------------------------
extern "C" void kernel_launch(void* const* d_in, const int* in_sizes, int n_in,
                              void* d_out, int out_size) {
    const float* x     = (const float*)d_in[0];
    const float* sigma = (const float*)d_in[1];
    float* out = (float*)d_out;

    weights_kernel<<<1, 128>>>(sigma);

    int hblocks = (NIMG * HH) / H_ROWS;          // 3072
    hpass_kernel<<<hblocks, 256>>>(x);

    dim3 vgrid(WW / V_COLS, HH / V_ROWS, NIMG);  // 16 x 8 x 24
    vpass_kernel<<<vgrid, 256>>>(out);
}

// round 4
// speedup vs baseline: 1.1496x; 1.1496x over previous
#include <cuda_runtime.h>

#define HH 512
#define WW 512
#define NIMG 24            // 8 * 3 planes
#define KS 121
#define MEANR 60
#define NSTEP 64           // pair-steps = 128 taps (121 real + 7 zero-pad)

typedef unsigned long long u64;

__device__ float g_tmp[NIMG * HH * WW];

// packed fp32x2 fma: a.xy += b.xy * c.xy  (Blackwell FFMA2, PTX-only)
__device__ __forceinline__ void ffma2(u64& a, u64 b, u64 c) {
    asm("fma.rn.f32x2 %0, %1, %2, %0;" : "+l"(a) : "l"(b), "l"(c));
}
__device__ __forceinline__ float2 u2f(u64 v) {
    float2 r;
    asm("mov.b64 {%0, %1}, %2;" : "=f"(r.x), "=f"(r.y) : "l"(v));
    return r;
}
__device__ __forceinline__ u64 f2u(float x, float y) {
    u64 r;
    asm("mov.b64 %0, {%1, %2};" : "=l"(r) : "f"(x), "f"(y));
    return r;
}

// Per-block weight prologue: compute duplicated-pair weights sw2[t]=(w,w).
// Threads 0..127 compute exp terms; warp 0 reduces; all write sw2.
__device__ __forceinline__ void make_weights(const float* sigma, u64* sw2,
                                             float* sred, int tid) {
    float e = 0.0f;
    if (tid < 128) {
        float s = sigma[0] * 8.0f + 16.0f;
        float d = (float)(tid - MEANR);
        e = (tid < KS) ? expf(-(d * d) / (2.0f * s * s)) : 0.0f;
        sred[tid] = e;
    }
    __syncthreads();
    if (tid < 32) {
        float s4 = sred[tid] + sred[tid + 32] + sred[tid + 64] + sred[tid + 96];
        #pragma unroll
        for (int off = 16; off > 0; off >>= 1)
            s4 += __shfl_xor_sync(0xffffffffu, s4, off);
        if (tid == 0) sred[0] = s4;
    }
    __syncthreads();
    if (tid < 128) {
        float wv = e / sred[0];   // zero for tid>=KS (e==0)
        sw2[tid] = f2u(wv, wv);
    }
}

// ---------------------------------------------------------------------------
// Horizontal pass: x -> g_tmp.
// Block = 8 warps, one warp per image row; lane l produces 16 outputs b=16l.
// Pairs P_k=(v[2k],v[2k+1]) in shared with pad p(k)=k+(k>>4)  -> conflict-free
// for the stride-8 pair bases. Even/odd tap-parity FFMA2 accumulation.
// ---------------------------------------------------------------------------
#define HP_PAIRS 320                 // covers v[0..639] per row
#define PADP(k) ((k) + ((k) >> 4))
#define HP_PHYS 340                  // PADP(319)=338, padded

__global__ __launch_bounds__(256) void hpass_kernel(const float* __restrict__ x,
                                                    const float* __restrict__ sigma) {
    __shared__ u64 sw2[128];
    __shared__ float sred[128];
    __shared__ u64 sp[8][HP_PHYS];

    int tid = threadIdx.x;
    int w = tid >> 5;
    int l = tid & 31;
    long row = (long)blockIdx.x * 8 + w;
    const float* xr = x + row * WW;

    // data load: pairs with replicate clamp
    for (int k = l; k < HP_PAIRS; k += 32) {
        int s0 = min(max(2 * k     - MEANR, 0), WW - 1);
        int s1 = min(max(2 * k + 1 - MEANR, 0), WW - 1);
        sp[w][PADP(k)] = f2u(xr[s0], xr[s1]);
    }
    make_weights(sigma, sw2, sred, tid);   // includes the needed __syncthreads
    __syncthreads();

    int b2 = l * 8;                        // pair base (output base b = 16l)
    u64 P[8];
    #pragma unroll
    for (int m = 0; m < 8; m++) P[m] = sp[w][PADP(b2 + m)];

    u64 accE[8], accQ[8];
    #pragma unroll
    for (int m = 0; m < 8; m++) { accE[m] = 0ull; accQ[m] = 0ull; }
    float qx = 0.0f;

    #pragma unroll 1
    for (int ss = 0; ss < NSTEP; ss += 8) {
        #pragma unroll
        for (int u = 0; u < 8; u++) {
            int s = ss + u;
            u64 we = sw2[2 * s];
            u64 wo = sw2[2 * s + 1];
            #pragma unroll
            for (int m = 0; m < 8; m++) {
                ffma2(accE[m], we, P[(u + m) & 7]);
                ffma2(accQ[m], wo, P[(u + m) & 7]);
            }
            u64 Pn = sp[w][PADP(b2 + s + 8)];
            float2 wof = u2f(wo);
            float2 Pnf = u2f(Pn);
            qx = fmaf(wof.x, Pnf.x, qx);   // q[b+16] boundary accumulator
            P[u & 7] = Pn;
        }
    }

    // recombine: out[i] = e[i] + q[i+1]
    float2* orow = (float2*)(g_tmp + row * WW + l * 16);
    #pragma unroll
    for (int m = 0; m < 8; m++) {
        float2 E = u2f(accE[m]);
        float2 Q = u2f(accQ[m]);
        float qn = (m < 7) ? u2f(accQ[m + 1]).x : qx;
        orow[m] = make_float2(E.x + Q.y, E.y + qn);
    }
}

// ---------------------------------------------------------------------------
// Vertical pass: g_tmp -> out.
// Tile 32 cols x 128 out-rows; thread (c, g) produces 16 rows at y0+16g.
// Shared holds transposed pairs spv[k][c], pair k = vertical (v[2k],v[2k+1]).
// Warp accesses consecutive c -> conflict-free (2-phase).
// ---------------------------------------------------------------------------
__global__ __launch_bounds__(256) void vpass_kernel(float* __restrict__ out,
                                                    const float* __restrict__ sigma) {
    __shared__ u64 sw2[128];
    __shared__ float sred[128];
    __shared__ u64 spv[128][32];   // 32 KB

    int tid = threadIdx.x;
    int img  = blockIdx.z;
    int col0 = blockIdx.x * 32;
    int y0   = blockIdx.y * 128;
    const float* tp = g_tmp + (long)img * HH * WW + col0;

    // load 256 y-rows x 32 cols, transposed into [pair][col] layout
    float* spf = (float*)spv;
    for (int idx = tid; idx < 256 * 32; idx += 256) {
        int yy = idx >> 5;
        int cc = idx & 31;
        int sy = min(max(y0 + yy - MEANR, 0), HH - 1);
        spf[((yy >> 1) * 32 + cc) * 2 + (yy & 1)] = tp[(long)sy * WW + cc];
    }
    make_weights(sigma, sw2, sred, tid);
    __syncthreads();

    int c = tid & 31;
    int g = tid >> 5;
    int b2 = g * 8;                 // pair base along y

    u64 P[8];
    #pragma unroll
    for (int m = 0; m < 8; m++) P[m] = spv[b2 + m][c];

    u64 accE[8], accQ[8];
    #pragma unroll
    for (int m = 0; m < 8; m++) { accE[m] = 0ull; accQ[m] = 0ull; }
    float qx = 0.0f;

    #pragma unroll 1
    for (int ss = 0; ss < NSTEP; ss += 8) {
        #pragma unroll
        for (int u = 0; u < 8; u++) {
            int s = ss + u;
            u64 we = sw2[2 * s];
            u64 wo = sw2[2 * s + 1];
            #pragma unroll
            for (int m = 0; m < 8; m++) {
                ffma2(accE[m], we, P[(u + m) & 7]);
                ffma2(accQ[m], wo, P[(u + m) & 7]);
            }
            u64 Pn = spv[b2 + s + 8][c];
            float2 wof = u2f(wo);
            float2 Pnf = u2f(Pn);
            qx = fmaf(wof.x, Pnf.x, qx);
            P[u & 7] = Pn;
        }
    }

    float* op = out + (long)img * HH * WW + (long)(y0 + g * 16) * WW + col0 + c;
    #pragma unroll
    for (int m = 0; m < 8; m++) {
        float2 E = u2f(accE[m]);
        float2 Q = u2f(accQ[m]);
        float qn = (m < 7) ? u2f(accQ[m + 1]).x : qx;
        op[(long)(2 * m)     * WW] = E.x + Q.y;
        op[(long)(2 * m + 1) * WW] = E.y + qn;
    }
}

// ---------------------------------------------------------------------------
extern "C" void kernel_launch(void* const* d_in, const int* in_sizes, int n_in,
                              void* d_out, int out_size) {
    const float* x     = (const float*)d_in[0];
    const float* sigma = (const float*)d_in[1];
    float* out = (float*)d_out;

    hpass_kernel<<<(NIMG * HH) / 8, 256>>>(x, sigma);          // 1536 blocks

    dim3 vgrid(WW / 32, HH / 128, NIMG);                        // 16 x 4 x 24
    vpass_kernel<<<vgrid, 256>>>(out, sigma);
}